// round 2
// baseline (speedup 1.0000x reference)
#include <cuda_runtime.h>
#include <math.h>

#define D_MODEL 1024
#define NH      16
#define DH      64
#define DFF     4096
#define BATCH   4
#define LSEQ    1024
#define MROWS   (BATCH*LSEQ)       // 4096
#define ZHEADS  (BATCH*NH)         // 64

// ---------------- scratch (device globals; no runtime allocation) ----------
__device__ float g_q[(size_t)ZHEADS*LSEQ*DH];          // (b,h,l,d)  16MB
__device__ float g_k[(size_t)ZHEADS*LSEQ*DH];
__device__ float g_v[(size_t)ZHEADS*LSEQ*DH];
__device__ float g_scores[(size_t)ZHEADS*LSEQ*LSEQ];   // 256MB
__device__ float g_heads[(size_t)MROWS*D_MODEL];       // (b,l, h*64+d)
__device__ float g_tmp[(size_t)MROWS*D_MODEL];
__device__ float g_h[(size_t)MROWS*D_MODEL];
__device__ float g_ff[(size_t)MROWS*DFF];              // 64MB

// ---------------- generic 128x128x16 SGEMM with epilogues -------------------
// C[M,N] = A[M,K] @ B[K,N] (+bias)(+resid), all row-major, dims % 128 == 0.
enum { EPI_SCATTER_HEADS = 0, EPI_BIAS_RESID = 1, EPI_BIAS_RELU = 2 };

template<int EPI>
__global__ __launch_bounds__(256) void sgemm128(
    const float* __restrict__ A, const float* __restrict__ B,
    float* __restrict__ C, int N, int K,
    const float* __restrict__ bias, const float* __restrict__ resid)
{
    __shared__ float As[16][128];
    __shared__ float Bs[16][128];

    const int tid   = threadIdx.x;
    const int tileM = blockIdx.y * 128;
    const int tileN = blockIdx.x * 128;
    const int m0 = (tid >> 4) * 8;
    const int n0 = (tid & 15) * 8;

    float acc[8][8];
#pragma unroll
    for (int i = 0; i < 8; i++)
#pragma unroll
        for (int j = 0; j < 8; j++) acc[i][j] = 0.f;

    const int arow = tid >> 2;          // 0..63
    const int ac4  = (tid & 3) * 4;     // 0,4,8,12
    const int brow = tid >> 5;          // 0..7
    const int bc4  = (tid & 31) * 4;    // 0..124

    for (int k0 = 0; k0 < K; k0 += 16) {
#pragma unroll
        for (int i = 0; i < 2; i++) {
            int r = arow + i * 64;
            float4 v = *(const float4*)(A + (size_t)(tileM + r) * K + k0 + ac4);
            As[ac4 + 0][r] = v.x; As[ac4 + 1][r] = v.y;
            As[ac4 + 2][r] = v.z; As[ac4 + 3][r] = v.w;
        }
#pragma unroll
        for (int i = 0; i < 2; i++) {
            int r = brow + i * 8;
            *(float4*)(&Bs[r][bc4]) =
                *(const float4*)(B + (size_t)(k0 + r) * N + tileN + bc4);
        }
        __syncthreads();
#pragma unroll
        for (int k = 0; k < 16; k++) {
            float ra[8], rb[8];
            *(float4*)(ra)     = *(const float4*)(&As[k][m0]);
            *(float4*)(ra + 4) = *(const float4*)(&As[k][m0 + 4]);
            *(float4*)(rb)     = *(const float4*)(&Bs[k][n0]);
            *(float4*)(rb + 4) = *(const float4*)(&Bs[k][n0 + 4]);
#pragma unroll
            for (int i = 0; i < 8; i++)
#pragma unroll
                for (int j = 0; j < 8; j++)
                    acc[i][j] += ra[i] * rb[j];
        }
        __syncthreads();
    }

#pragma unroll
    for (int i = 0; i < 8; i++) {
        const int m = tileM + m0 + i;
#pragma unroll
        for (int j = 0; j < 8; j++) {
            const int n = tileN + n0 + j;
            float v = acc[i][j];
            if (EPI == EPI_SCATTER_HEADS) {
                // (m = b*1024+l, n = h*64+d) -> q/k/v[(b*16+h)*1024 + l][d]
                int b = m >> 10, l = m & 1023, h = n >> 6, d = n & 63;
                C[((size_t)((b * NH + h) * LSEQ + l)) * DH + d] = v;
            } else if (EPI == EPI_BIAS_RESID) {
                size_t idx = (size_t)m * N + n;
                C[idx] = v + bias[n] + resid[idx];
            } else { // EPI_BIAS_RELU
                size_t idx = (size_t)m * N + n;
                float t = v + bias[n];
                C[idx] = t > 0.f ? t : 0.f;
            }
        }
    }
}

// ---------------- attention: scores = (Q K^T) / 8 ---------------------------
__global__ __launch_bounds__(256) void attn_scores(
    const float* __restrict__ Q, const float* __restrict__ Km,
    float* __restrict__ S)
{
    __shared__ float qt[32][128];
    __shared__ float kt[32][128];

    const int z = blockIdx.z;
    const float* q  = Q  + (size_t)z * LSEQ * DH;
    const float* kp = Km + (size_t)z * LSEQ * DH;
    float*       s  = S  + (size_t)z * LSEQ * LSEQ;

    const int tileQ = blockIdx.y * 128;
    const int tileK = blockIdx.x * 128;
    const int tid = threadIdx.x;
    const int m0 = (tid >> 4) * 8;
    const int n0 = (tid & 15) * 8;

    float acc[8][8];
#pragma unroll
    for (int i = 0; i < 8; i++)
#pragma unroll
        for (int j = 0; j < 8; j++) acc[i][j] = 0.f;

    for (int d0 = 0; d0 < DH; d0 += 32) {
#pragma unroll
        for (int it = 0; it < 4; it++) {
            int idx = it * 256 + tid;
            int row = idx >> 3;           // 0..127
            int c4  = (idx & 7) * 4;      // 0..28
            float4 a = *(const float4*)(q  + (size_t)(tileQ + row) * DH + d0 + c4);
            qt[c4 + 0][row] = a.x; qt[c4 + 1][row] = a.y;
            qt[c4 + 2][row] = a.z; qt[c4 + 3][row] = a.w;
            float4 b = *(const float4*)(kp + (size_t)(tileK + row) * DH + d0 + c4);
            kt[c4 + 0][row] = b.x; kt[c4 + 1][row] = b.y;
            kt[c4 + 2][row] = b.z; kt[c4 + 3][row] = b.w;
        }
        __syncthreads();
#pragma unroll
        for (int d = 0; d < 32; d++) {
            float ra[8], rb[8];
            *(float4*)(ra)     = *(const float4*)(&qt[d][m0]);
            *(float4*)(ra + 4) = *(const float4*)(&qt[d][m0 + 4]);
            *(float4*)(rb)     = *(const float4*)(&kt[d][n0]);
            *(float4*)(rb + 4) = *(const float4*)(&kt[d][n0 + 4]);
#pragma unroll
            for (int i = 0; i < 8; i++)
#pragma unroll
                for (int j = 0; j < 8; j++)
                    acc[i][j] += ra[i] * rb[j];
        }
        __syncthreads();
    }

#pragma unroll
    for (int i = 0; i < 8; i++)
#pragma unroll
        for (int j = 0; j < 8; j++)
            s[(size_t)(tileQ + m0 + i) * LSEQ + tileK + n0 + j] = acc[i][j] * 0.125f;
}

// ---------------- masked row softmax (in place) -----------------------------
__global__ __launch_bounds__(256) void softmax_mask(
    float* __restrict__ S, const int* __restrict__ mask)
{
    __shared__ float red[8];
    const size_t r = blockIdx.x;                 // 0..65535 = (b*16+h)*1024 + q
    const int b = (int)(r >> 14);
    float* row = S + r * LSEQ;
    const int* mrow = mask + (size_t)b * LSEQ;
    const int tid = threadIdx.x;

    float4 v = *(const float4*)(row + tid * 4);
    int4  mv = *(const int4*)(mrow + tid * 4);
    if (mv.x == 0) v.x = -1e10f;
    if (mv.y == 0) v.y = -1e10f;
    if (mv.z == 0) v.z = -1e10f;
    if (mv.w == 0) v.w = -1e10f;

    float mx = fmaxf(fmaxf(v.x, v.y), fmaxf(v.z, v.w));
#pragma unroll
    for (int o = 16; o > 0; o >>= 1) mx = fmaxf(mx, __shfl_xor_sync(0xffffffffu, mx, o));
    if ((tid & 31) == 0) red[tid >> 5] = mx;
    __syncthreads();
    mx = red[0];
#pragma unroll
    for (int i = 1; i < 8; i++) mx = fmaxf(mx, red[i]);
    __syncthreads();

    v.x = __expf(v.x - mx); v.y = __expf(v.y - mx);
    v.z = __expf(v.z - mx); v.w = __expf(v.w - mx);
    float sm = v.x + v.y + v.z + v.w;
#pragma unroll
    for (int o = 16; o > 0; o >>= 1) sm += __shfl_xor_sync(0xffffffffu, sm, o);
    if ((tid & 31) == 0) red[tid >> 5] = sm;
    __syncthreads();
    sm = 0.f;
#pragma unroll
    for (int i = 0; i < 8; i++) sm += red[i];
    float inv = 1.f / sm;
    v.x *= inv; v.y *= inv; v.z *= inv; v.w *= inv;
    *(float4*)(row + tid * 4) = v;
}

// ---------------- attention: heads = P @ V, scattered to (B,L,D) ------------
__global__ __launch_bounds__(256) void attn_av(
    const float* __restrict__ P, const float* __restrict__ V,
    float* __restrict__ H)
{
    __shared__ float As[32][64];
    __shared__ float Bs[32][64];

    const int z = blockIdx.y;
    const int b = z >> 4, h = z & 15;
    const float* p = P + (size_t)z * LSEQ * LSEQ;
    const float* v = V + (size_t)z * LSEQ * DH;
    const int tileM = blockIdx.x * 64;
    const int tid = threadIdx.x;
    const int m0 = (tid >> 4) * 4;
    const int n0 = (tid & 15) * 4;

    float acc[4][4];
#pragma unroll
    for (int i = 0; i < 4; i++)
#pragma unroll
        for (int j = 0; j < 4; j++) acc[i][j] = 0.f;

    for (int k0 = 0; k0 < LSEQ; k0 += 32) {
#pragma unroll
        for (int it = 0; it < 2; it++) {
            int idx = it * 256 + tid;
            int row = idx >> 3, c4 = (idx & 7) * 4;        // A: 64 x 32
            float4 a = *(const float4*)(p + (size_t)(tileM + row) * LSEQ + k0 + c4);
            As[c4 + 0][row] = a.x; As[c4 + 1][row] = a.y;
            As[c4 + 2][row] = a.z; As[c4 + 3][row] = a.w;
            int brow = idx >> 4, bc4 = (idx & 15) * 4;     // B: 32 x 64
            *(float4*)(&Bs[brow][bc4]) =
                *(const float4*)(v + (size_t)(k0 + brow) * DH + bc4);
        }
        __syncthreads();
#pragma unroll
        for (int k = 0; k < 32; k++) {
            float ra[4], rb[4];
            *(float4*)(ra) = *(const float4*)(&As[k][m0]);
            *(float4*)(rb) = *(const float4*)(&Bs[k][n0]);
#pragma unroll
            for (int i = 0; i < 4; i++)
#pragma unroll
                for (int j = 0; j < 4; j++)
                    acc[i][j] += ra[i] * rb[j];
        }
        __syncthreads();
    }

#pragma unroll
    for (int i = 0; i < 4; i++) {
        int l = tileM + m0 + i;
#pragma unroll
        for (int j = 0; j < 4; j++)
            H[(size_t)(b * LSEQ + l) * D_MODEL + h * DH + n0 + j] = acc[i][j];
    }
}

// ---------------- layernorm --------------------------------------------------
__global__ __launch_bounds__(256) void layernorm(
    const float* __restrict__ X, const float* __restrict__ g,
    const float* __restrict__ be, float* __restrict__ O)
{
    __shared__ float red[8];
    const int r = blockIdx.x;
    const int tid = threadIdx.x;
    const float4 v = *(const float4*)(X + (size_t)r * D_MODEL + tid * 4);

    float s = v.x + v.y + v.z + v.w;
#pragma unroll
    for (int o = 16; o > 0; o >>= 1) s += __shfl_xor_sync(0xffffffffu, s, o);
    if ((tid & 31) == 0) red[tid >> 5] = s;
    __syncthreads();
    s = 0.f;
#pragma unroll
    for (int i = 0; i < 8; i++) s += red[i];
    const float mu = s * (1.f / D_MODEL);
    __syncthreads();

    float dx = v.x - mu, dy = v.y - mu, dz = v.z - mu, dw = v.w - mu;
    float sq = dx * dx + dy * dy + dz * dz + dw * dw;
#pragma unroll
    for (int o = 16; o > 0; o >>= 1) sq += __shfl_xor_sync(0xffffffffu, sq, o);
    if ((tid & 31) == 0) red[tid >> 5] = sq;
    __syncthreads();
    sq = 0.f;
#pragma unroll
    for (int i = 0; i < 8; i++) sq += red[i];
    const float rs = rsqrtf(sq * (1.f / D_MODEL) + 1e-5f);

    const float4 gg = *(const float4*)(g + tid * 4);
    const float4 bb = *(const float4*)(be + tid * 4);
    float4 o;
    o.x = dx * rs * gg.x + bb.x;
    o.y = dy * rs * gg.y + bb.y;
    o.z = dz * rs * gg.z + bb.z;
    o.w = dw * rs * gg.w + bb.w;
    *(float4*)(O + (size_t)r * D_MODEL + tid * 4) = o;
}

// ---------------- launch -----------------------------------------------------
extern "C" void kernel_launch(void* const* d_in, const int* in_sizes, int n_in,
                              void* d_out, int out_size)
{
    const float* x   = (const float*)d_in[0];
    const int*   msk = (const int*)d_in[1];
    const float* Wq  = (const float*)d_in[2];
    const float* Wk  = (const float*)d_in[3];
    const float* Wv  = (const float*)d_in[4];
    const float* Wp  = (const float*)d_in[5];
    const float* bp  = (const float*)d_in[6];
    const float* W1  = (const float*)d_in[7];
    const float* b1  = (const float*)d_in[8];
    const float* W2  = (const float*)d_in[9];
    const float* b2  = (const float*)d_in[10];
    const float* g1  = (const float*)d_in[11];
    const float* be1 = (const float*)d_in[12];
    const float* g2  = (const float*)d_in[13];
    const float* be2 = (const float*)d_in[14];
    float* out = (float*)d_out;

    float *q, *k, *v, *sc, *hd, *tmp, *h, *ff;
    cudaGetSymbolAddress((void**)&q,   g_q);
    cudaGetSymbolAddress((void**)&k,   g_k);
    cudaGetSymbolAddress((void**)&v,   g_v);
    cudaGetSymbolAddress((void**)&sc,  g_scores);
    cudaGetSymbolAddress((void**)&hd,  g_heads);
    cudaGetSymbolAddress((void**)&tmp, g_tmp);
    cudaGetSymbolAddress((void**)&h,   g_h);
    cudaGetSymbolAddress((void**)&ff,  g_ff);

    dim3 blk(256);

    // Q/K/V projections, scattered into per-head layout
    sgemm128<EPI_SCATTER_HEADS><<<dim3(8, 32), blk>>>(x, Wq, q, D_MODEL, D_MODEL, nullptr, nullptr);
    sgemm128<EPI_SCATTER_HEADS><<<dim3(8, 32), blk>>>(x, Wk, k, D_MODEL, D_MODEL, nullptr, nullptr);
    sgemm128<EPI_SCATTER_HEADS><<<dim3(8, 32), blk>>>(x, Wv, v, D_MODEL, D_MODEL, nullptr, nullptr);

    // scores = QK^T / 8, softmax(mask), heads = P V
    attn_scores<<<dim3(8, 8, ZHEADS), blk>>>(q, k, sc);
    softmax_mask<<<ZHEADS * LSEQ, blk>>>(sc, msk);
    attn_av<<<dim3(16, ZHEADS), blk>>>(sc, v, hd);

    // proj + residual, LN1
    sgemm128<EPI_BIAS_RESID><<<dim3(8, 32), blk>>>(hd, Wp, tmp, D_MODEL, D_MODEL, bp, x);
    layernorm<<<MROWS, blk>>>(tmp, g1, be1, h);

    // FF1 (ReLU), FF2 + residual, LN2
    sgemm128<EPI_BIAS_RELU><<<dim3(32, 32), blk>>>(h, W1, ff, DFF, D_MODEL, b1, nullptr);
    sgemm128<EPI_BIAS_RESID><<<dim3(8, 32), blk>>>(ff, W2, tmp, D_MODEL, DFF, b2, h);
    layernorm<<<MROWS, blk>>>(tmp, g2, be2, out);
}

// round 4
// speedup vs baseline: 3.2639x; 3.2639x over previous
#include <cuda_runtime.h>
#include <cstdint>
#include <math.h>

#define D_MODEL 1024
#define NH      16
#define DH      64
#define DFF     4096
#define BATCH   4
#define LSEQ    1024
#define MROWS   (BATCH*LSEQ)       // 4096
#define ZHEADS  (BATCH*NH)         // 64

// ---------------- scratch (device globals; no runtime allocation) ----------
__device__ float g_q[(size_t)ZHEADS*LSEQ*DH];          // (b,h,l,d)
__device__ float g_k[(size_t)ZHEADS*LSEQ*DH];
__device__ float g_v[(size_t)ZHEADS*LSEQ*DH];
__device__ float g_scores[(size_t)ZHEADS*LSEQ*LSEQ];   // 256MB
__device__ float g_heads[(size_t)MROWS*D_MODEL];
__device__ float g_tmp[(size_t)MROWS*D_MODEL];
__device__ float g_h[(size_t)MROWS*D_MODEL];
__device__ float g_ff[(size_t)MROWS*DFF];
__device__ float g_wtqkv[(size_t)3*D_MODEL*D_MODEL];   // [3*1024][1024] (N,K)
__device__ float g_wtp[(size_t)D_MODEL*D_MODEL];
__device__ float g_wt1[(size_t)DFF*D_MODEL];           // [4096][1024]
__device__ float g_wt2[(size_t)D_MODEL*DFF];           // [1024][4096]

// ---------------- helpers ----------------------------------------------------
__device__ __forceinline__ float f2tf32(float f) {
    uint32_t r;
    asm("cvt.rna.tf32.f32 %0, %1;" : "=r"(r) : "f"(f));
    return __uint_as_float(r);
}
__device__ __forceinline__ void mma_tf32(float* d, const uint32_t* a,
                                         const uint32_t* b) {
    asm volatile(
        "mma.sync.aligned.m16n8k8.row.col.f32.tf32.tf32.f32 "
        "{%0,%1,%2,%3}, {%4,%5,%6,%7}, {%8,%9}, {%0,%1,%2,%3};"
        : "+f"(d[0]), "+f"(d[1]), "+f"(d[2]), "+f"(d[3])
        : "r"(a[0]), "r"(a[1]), "r"(a[2]), "r"(a[3]), "r"(b[0]), "r"(b[1]));
}

// ---------------- tf32 mma GEMM: C = A[M,K] @ BT[N,K]^T ---------------------
// 128x128 CTA tile, 8 warps (2x4), warp tile 64x32, K-chunk 32.
enum { EPI_QKV = 0, EPI_BIAS_RESID = 1, EPI_BIAS_RELU = 2, EPI_SCORES = 3 };

template<int EPI>
__global__ __launch_bounds__(256) void gemm_mma(
    const float* __restrict__ A, const float* __restrict__ BT,
    float* __restrict__ C, int N, int K,
    long long sAz, long long sBz, long long sCz,
    const float* __restrict__ bias, const float* __restrict__ resid,
    float* __restrict__ qp, float* __restrict__ kp, float* __restrict__ vp)
{
    __shared__ float As[128][36];
    __shared__ float Bs[128][36];

    const float* Ab = A  + (size_t)blockIdx.z * sAz;
    const float* Bb = BT + (size_t)blockIdx.z * sBz;
    float*       Cb = C  + (size_t)blockIdx.z * sCz;

    const int tid  = threadIdx.x;
    const int wid  = tid >> 5;
    const int lane = tid & 31;
    const int g    = lane >> 2;
    const int t4   = lane & 3;
    const int wm   = wid >> 2;          // 0..1  (64-row slab)
    const int wn   = wid & 3;           // 0..3  (32-col slab)
    const int tileM = blockIdx.y * 128;
    const int tileN = blockIdx.x * 128;

    float acc[4][4][4];
#pragma unroll
    for (int i = 0; i < 4; i++)
#pragma unroll
        for (int j = 0; j < 4; j++)
#pragma unroll
            for (int c = 0; c < 4; c++) acc[i][j][c] = 0.f;

    for (int k0 = 0; k0 < K; k0 += 32) {
        // fill 128x32 tiles of A and BT (tf32-rounded)
#pragma unroll
        for (int i = 0; i < 4; i++) {
            const int idx = i * 256 + tid;
            const int r   = idx >> 3;
            const int c4  = (idx & 7) * 4;
            float4 av = *(const float4*)(Ab + (size_t)(tileM + r) * K + k0 + c4);
            As[r][c4 + 0] = f2tf32(av.x); As[r][c4 + 1] = f2tf32(av.y);
            As[r][c4 + 2] = f2tf32(av.z); As[r][c4 + 3] = f2tf32(av.w);
            float4 bv = *(const float4*)(Bb + (size_t)(tileN + r) * K + k0 + c4);
            Bs[r][c4 + 0] = f2tf32(bv.x); Bs[r][c4 + 1] = f2tf32(bv.y);
            Bs[r][c4 + 2] = f2tf32(bv.z); Bs[r][c4 + 3] = f2tf32(bv.w);
        }
        __syncthreads();

#pragma unroll
        for (int ks = 0; ks < 4; ks++) {
            const int k = ks * 8;
            uint32_t af[4][4], bf[4][2];
#pragma unroll
            for (int mi = 0; mi < 4; mi++) {
                const int rb = wm * 64 + mi * 16;
                af[mi][0] = __float_as_uint(As[rb + g    ][k + t4    ]);
                af[mi][1] = __float_as_uint(As[rb + g + 8][k + t4    ]);
                af[mi][2] = __float_as_uint(As[rb + g    ][k + t4 + 4]);
                af[mi][3] = __float_as_uint(As[rb + g + 8][k + t4 + 4]);
            }
#pragma unroll
            for (int ni = 0; ni < 4; ni++) {
                const int nb = wn * 32 + ni * 8;
                bf[ni][0] = __float_as_uint(Bs[nb + g][k + t4    ]);
                bf[ni][1] = __float_as_uint(Bs[nb + g][k + t4 + 4]);
            }
#pragma unroll
            for (int mi = 0; mi < 4; mi++)
#pragma unroll
                for (int ni = 0; ni < 4; ni++)
                    mma_tf32(acc[mi][ni], af[mi], bf[ni]);
        }
        __syncthreads();
    }

    // epilogue
#pragma unroll
    for (int mi = 0; mi < 4; mi++) {
#pragma unroll
        for (int half = 0; half < 2; half++) {
            const int m = tileM + wm * 64 + mi * 16 + g + half * 8;
#pragma unroll
            for (int ni = 0; ni < 4; ni++) {
                const int n = tileN + wn * 32 + ni * 8 + t4 * 2;
                float v0 = acc[mi][ni][half * 2 + 0];
                float v1 = acc[mi][ni][half * 2 + 1];
                if (EPI == EPI_SCORES) {
                    float2 o = make_float2(v0 * 0.125f, v1 * 0.125f);
                    *(float2*)(Cb + (size_t)m * N + n) = o;
                } else if (EPI == EPI_QKV) {
                    const int b = m >> 10, l = m & 1023;
                    const int which = n >> 10, rem = n & 1023;
                    const int h = rem >> 6, d = rem & 63;
                    float* dst = (which == 0) ? qp : (which == 1) ? kp : vp;
                    float2 o = make_float2(v0, v1);
                    *(float2*)(dst + ((size_t)((b * NH + h) * LSEQ + l)) * DH + d) = o;
                } else {
                    const size_t idx = (size_t)m * N + n;
                    const float2 bb = *(const float2*)(bias + n);
                    v0 += bb.x; v1 += bb.y;
                    if (EPI == EPI_BIAS_RESID) {
                        const float2 rr = *(const float2*)(resid + idx);
                        v0 += rr.x; v1 += rr.y;
                    } else {
                        v0 = fmaxf(v0, 0.f); v1 = fmaxf(v1, 0.f);
                    }
                    *(float2*)(Cb + idx) = make_float2(v0, v1);
                }
            }
        }
    }
}

// ---------------- P @ V via mma: tile 256x64, warps 4x2 ---------------------
__global__ __launch_bounds__(256) void attn_av_mma(
    const float* __restrict__ P, const float* __restrict__ V,
    float* __restrict__ H)
{
    __shared__ float Ps[256][36];
    __shared__ float Vs[32][68];

    const int z = blockIdx.y;
    const int b = z >> 4, h = z & 15;
    const float* p = P + (size_t)z * LSEQ * LSEQ;
    const float* v = V + (size_t)z * LSEQ * DH;

    const int tid  = threadIdx.x;
    const int wid  = tid >> 5;
    const int lane = tid & 31;
    const int g    = lane >> 2;
    const int t4   = lane & 3;
    const int wm   = wid >> 1;          // 0..3 (64-row slab)
    const int wn   = wid & 1;           // 0..1 (32-col slab)
    const int tileM = blockIdx.x * 256;

    float acc[4][4][4];
#pragma unroll
    for (int i = 0; i < 4; i++)
#pragma unroll
        for (int j = 0; j < 4; j++)
#pragma unroll
            for (int c = 0; c < 4; c++) acc[i][j][c] = 0.f;

    for (int k0 = 0; k0 < LSEQ; k0 += 32) {
        // P tile 256x32
#pragma unroll
        for (int i = 0; i < 8; i++) {
            const int idx = i * 256 + tid;
            const int r   = idx >> 3;
            const int c4  = (idx & 7) * 4;
            float4 a = *(const float4*)(p + (size_t)(tileM + r) * LSEQ + k0 + c4);
            Ps[r][c4 + 0] = f2tf32(a.x); Ps[r][c4 + 1] = f2tf32(a.y);
            Ps[r][c4 + 2] = f2tf32(a.z); Ps[r][c4 + 3] = f2tf32(a.w);
        }
        // V tile 32x64 in native [k][n] layout
#pragma unroll
        for (int i = 0; i < 2; i++) {
            const int idx = i * 256 + tid;
            const int r   = idx >> 4;
            const int c4  = (idx & 15) * 4;
            float4 bv = *(const float4*)(v + (size_t)(k0 + r) * DH + c4);
            Vs[r][c4 + 0] = f2tf32(bv.x); Vs[r][c4 + 1] = f2tf32(bv.y);
            Vs[r][c4 + 2] = f2tf32(bv.z); Vs[r][c4 + 3] = f2tf32(bv.w);
        }
        __syncthreads();

#pragma unroll
        for (int ks = 0; ks < 4; ks++) {
            const int k = ks * 8;
            uint32_t af[4][4], bf[4][2];
#pragma unroll
            for (int mi = 0; mi < 4; mi++) {
                const int rb = wm * 64 + mi * 16;
                af[mi][0] = __float_as_uint(Ps[rb + g    ][k + t4    ]);
                af[mi][1] = __float_as_uint(Ps[rb + g + 8][k + t4    ]);
                af[mi][2] = __float_as_uint(Ps[rb + g    ][k + t4 + 4]);
                af[mi][3] = __float_as_uint(Ps[rb + g + 8][k + t4 + 4]);
            }
#pragma unroll
            for (int ni = 0; ni < 4; ni++) {
                const int nb = wn * 32 + ni * 8;
                bf[ni][0] = __float_as_uint(Vs[k + t4    ][nb + g]);
                bf[ni][1] = __float_as_uint(Vs[k + t4 + 4][nb + g]);
            }
#pragma unroll
            for (int mi = 0; mi < 4; mi++)
#pragma unroll
                for (int ni = 0; ni < 4; ni++)
                    mma_tf32(acc[mi][ni], af[mi], bf[ni]);
        }
        __syncthreads();
    }

#pragma unroll
    for (int mi = 0; mi < 4; mi++) {
#pragma unroll
        for (int half = 0; half < 2; half++) {
            const int l = tileM + wm * 64 + mi * 16 + g + half * 8;
#pragma unroll
            for (int ni = 0; ni < 4; ni++) {
                const int d = wn * 32 + ni * 8 + t4 * 2;
                float2 o = make_float2(acc[mi][ni][half * 2 + 0],
                                       acc[mi][ni][half * 2 + 1]);
                *(float2*)(H + (size_t)(b * LSEQ + l) * D_MODEL + h * DH + d) = o;
            }
        }
    }
}

// ---------------- weight transpose: out[n][k] = in[k][n] --------------------
__global__ __launch_bounds__(256) void transpose_k(
    const float* __restrict__ in, float* __restrict__ out, int K, int N)
{
    __shared__ float t[32][33];
    const int bn = blockIdx.x * 32, bk = blockIdx.y * 32;
    const int tx = threadIdx.x, ty = threadIdx.y;
#pragma unroll
    for (int i = ty; i < 32; i += 8)
        t[i][tx] = in[(size_t)(bk + i) * N + bn + tx];
    __syncthreads();
#pragma unroll
    for (int i = ty; i < 32; i += 8)
        out[(size_t)(bn + i) * K + bk + tx] = t[tx][i];
}

// ---------------- masked row softmax (in place) -----------------------------
__global__ __launch_bounds__(256) void softmax_mask(
    float* __restrict__ S, const int* __restrict__ mask)
{
    __shared__ float red[8];
    const size_t r = blockIdx.x;
    const int b = (int)(r >> 14);
    float* row = S + r * LSEQ;
    const int* mrow = mask + (size_t)b * LSEQ;
    const int tid = threadIdx.x;

    float4 v = *(const float4*)(row + tid * 4);
    int4  mv = *(const int4*)(mrow + tid * 4);
    if (mv.x == 0) v.x = -1e10f;
    if (mv.y == 0) v.y = -1e10f;
    if (mv.z == 0) v.z = -1e10f;
    if (mv.w == 0) v.w = -1e10f;

    float mx = fmaxf(fmaxf(v.x, v.y), fmaxf(v.z, v.w));
#pragma unroll
    for (int o = 16; o > 0; o >>= 1) mx = fmaxf(mx, __shfl_xor_sync(0xffffffffu, mx, o));
    if ((tid & 31) == 0) red[tid >> 5] = mx;
    __syncthreads();
    mx = red[0];
#pragma unroll
    for (int i = 1; i < 8; i++) mx = fmaxf(mx, red[i]);
    __syncthreads();

    v.x = __expf(v.x - mx); v.y = __expf(v.y - mx);
    v.z = __expf(v.z - mx); v.w = __expf(v.w - mx);
    float sm = v.x + v.y + v.z + v.w;
#pragma unroll
    for (int o = 16; o > 0; o >>= 1) sm += __shfl_xor_sync(0xffffffffu, sm, o);
    if ((tid & 31) == 0) red[tid >> 5] = sm;
    __syncthreads();
    sm = 0.f;
#pragma unroll
    for (int i = 0; i < 8; i++) sm += red[i];
    float inv = 1.f / sm;
    v.x *= inv; v.y *= inv; v.z *= inv; v.w *= inv;
    *(float4*)(row + tid * 4) = v;
}

// ---------------- layernorm --------------------------------------------------
__global__ __launch_bounds__(256) void layernorm(
    const float* __restrict__ X, const float* __restrict__ g,
    const float* __restrict__ be, float* __restrict__ O)
{
    __shared__ float red[8];
    const int r = blockIdx.x;
    const int tid = threadIdx.x;
    const float4 v = *(const float4*)(X + (size_t)r * D_MODEL + tid * 4);

    float s = v.x + v.y + v.z + v.w;
#pragma unroll
    for (int o = 16; o > 0; o >>= 1) s += __shfl_xor_sync(0xffffffffu, s, o);
    if ((tid & 31) == 0) red[tid >> 5] = s;
    __syncthreads();
    s = 0.f;
#pragma unroll
    for (int i = 0; i < 8; i++) s += red[i];
    const float mu = s * (1.f / D_MODEL);
    __syncthreads();

    float dx = v.x - mu, dy = v.y - mu, dz = v.z - mu, dw = v.w - mu;
    float sq = dx * dx + dy * dy + dz * dz + dw * dw;
#pragma unroll
    for (int o = 16; o > 0; o >>= 1) sq += __shfl_xor_sync(0xffffffffu, sq, o);
    if ((tid & 31) == 0) red[tid >> 5] = sq;
    __syncthreads();
    sq = 0.f;
#pragma unroll
    for (int i = 0; i < 8; i++) sq += red[i];
    const float rs = rsqrtf(sq * (1.f / D_MODEL) + 1e-5f);

    const float4 gg = *(const float4*)(g + tid * 4);
    const float4 bb = *(const float4*)(be + tid * 4);
    float4 o;
    o.x = dx * rs * gg.x + bb.x;
    o.y = dy * rs * gg.y + bb.y;
    o.z = dz * rs * gg.z + bb.z;
    o.w = dw * rs * gg.w + bb.w;
    *(float4*)(O + (size_t)r * D_MODEL + tid * 4) = o;
}

// ---------------- launch -----------------------------------------------------
extern "C" void kernel_launch(void* const* d_in, const int* in_sizes, int n_in,
                              void* d_out, int out_size)
{
    const float* x   = (const float*)d_in[0];
    const int*   msk = (const int*)d_in[1];
    const float* Wq  = (const float*)d_in[2];
    const float* Wk  = (const float*)d_in[3];
    const float* Wv  = (const float*)d_in[4];
    const float* Wp  = (const float*)d_in[5];
    const float* bp  = (const float*)d_in[6];
    const float* W1  = (const float*)d_in[7];
    const float* b1  = (const float*)d_in[8];
    const float* W2  = (const float*)d_in[9];
    const float* b2  = (const float*)d_in[10];
    const float* g1  = (const float*)d_in[11];
    const float* be1 = (const float*)d_in[12];
    const float* g2  = (const float*)d_in[13];
    const float* be2 = (const float*)d_in[14];
    float* out = (float*)d_out;

    float *q, *k, *v, *sc, *hd, *tmp, *h, *ff, *wtqkv, *wtp, *wt1, *wt2;
    cudaGetSymbolAddress((void**)&q,     g_q);
    cudaGetSymbolAddress((void**)&k,     g_k);
    cudaGetSymbolAddress((void**)&v,     g_v);
    cudaGetSymbolAddress((void**)&sc,    g_scores);
    cudaGetSymbolAddress((void**)&hd,    g_heads);
    cudaGetSymbolAddress((void**)&tmp,   g_tmp);
    cudaGetSymbolAddress((void**)&h,     g_h);
    cudaGetSymbolAddress((void**)&ff,    g_ff);
    cudaGetSymbolAddress((void**)&wtqkv, g_wtqkv);
    cudaGetSymbolAddress((void**)&wtp,   g_wtp);
    cudaGetSymbolAddress((void**)&wt1,   g_wt1);
    cudaGetSymbolAddress((void**)&wt2,   g_wt2);

    dim3 blk(256);
    dim3 tb(32, 8);

    // weight transposes -> (N,K) layouts
    transpose_k<<<dim3(32, 32), tb>>>(Wq, wtqkv + 0 * 1024 * 1024, D_MODEL, D_MODEL);
    transpose_k<<<dim3(32, 32), tb>>>(Wk, wtqkv + 1 * 1024 * 1024, D_MODEL, D_MODEL);
    transpose_k<<<dim3(32, 32), tb>>>(Wv, wtqkv + 2 * 1024 * 1024, D_MODEL, D_MODEL);
    transpose_k<<<dim3(32, 32), tb>>>(Wp, wtp, D_MODEL, D_MODEL);
    transpose_k<<<dim3(128, 32), tb>>>(W1, wt1, D_MODEL, DFF);   // 1024x4096 -> 4096x1024
    transpose_k<<<dim3(32, 128), tb>>>(W2, wt2, DFF, D_MODEL);   // 4096x1024 -> 1024x4096

    // fused QKV projection (M=4096, N=3072, K=1024), scatter to head layout
    gemm_mma<EPI_QKV><<<dim3(24, 32, 1), blk>>>(
        x, wtqkv, nullptr, 3072, 1024, 0, 0, 0, nullptr, nullptr, q, k, v);

    // scores = QK^T / 8 (batched per head, K=64)
    gemm_mma<EPI_SCORES><<<dim3(8, 8, ZHEADS), blk>>>(
        q, k, sc, LSEQ, DH,
        (long long)LSEQ * DH, (long long)LSEQ * DH, (long long)LSEQ * LSEQ,
        nullptr, nullptr, nullptr, nullptr, nullptr);

    softmax_mask<<<ZHEADS * LSEQ, blk>>>(sc, msk);

    // heads = P @ V (per head, tile 256x64)
    attn_av_mma<<<dim3(4, ZHEADS), blk>>>(sc, v, hd);

    // proj + bias + residual, LN1
    gemm_mma<EPI_BIAS_RESID><<<dim3(8, 32, 1), blk>>>(
        hd, wtp, tmp, 1024, 1024, 0, 0, 0, bp, x, nullptr, nullptr, nullptr);
    layernorm<<<MROWS, blk>>>(tmp, g1, be1, h);

    // FF1 (ReLU), FF2 + bias + residual, LN2
    gemm_mma<EPI_BIAS_RELU><<<dim3(32, 32, 1), blk>>>(
        h, wt1, ff, 4096, 1024, 0, 0, 0, b1, nullptr, nullptr, nullptr, nullptr);
    gemm_mma<EPI_BIAS_RESID><<<dim3(8, 32, 1), blk>>>(
        ff, wt2, tmp, 1024, 4096, 0, 0, 0, b2, h, nullptr, nullptr, nullptr);
    layernorm<<<MROWS, blk>>>(tmp, g2, be2, out);
}

// round 5
// speedup vs baseline: 4.2757x; 1.3100x over previous
#include <cuda_runtime.h>
#include <cstdint>
#include <math.h>

#define D_MODEL 1024
#define NH      16
#define DH      64
#define DFF     4096
#define BATCH   4
#define LSEQ    1024
#define MROWS   (BATCH*LSEQ)       // 4096
#define ZHEADS  (BATCH*NH)         // 64

// ---------------- scratch (device globals; no runtime allocation) ----------
__device__ float g_q[(size_t)ZHEADS*LSEQ*DH];          // (b,h,l,d)
__device__ float g_k[(size_t)ZHEADS*LSEQ*DH];
__device__ float g_v[(size_t)ZHEADS*LSEQ*DH];
__device__ float g_scores[(size_t)ZHEADS*LSEQ*LSEQ];   // 256MB
__device__ float g_heads[(size_t)MROWS*D_MODEL];
__device__ float g_tmp[(size_t)MROWS*D_MODEL];
__device__ float g_h[(size_t)MROWS*D_MODEL];
__device__ float g_ff[(size_t)MROWS*DFF];
__device__ float g_wtqkv[(size_t)3*D_MODEL*D_MODEL];   // [3*1024][1024] (N,K)
__device__ float g_wtp[(size_t)D_MODEL*D_MODEL];
__device__ float g_wt1[(size_t)DFF*D_MODEL];           // [4096][1024]
__device__ float g_wt2[(size_t)D_MODEL*DFF];           // [1024][4096]

// ---------------- helpers ----------------------------------------------------
__device__ __forceinline__ float f2tf32(float f) {
    uint32_t r;
    asm("cvt.rna.tf32.f32 %0, %1;" : "=r"(r) : "f"(f));
    return __uint_as_float(r);
}
__device__ __forceinline__ void mma_tf32(float* d, const uint32_t* a,
                                         const uint32_t* b) {
    asm volatile(
        "mma.sync.aligned.m16n8k8.row.col.f32.tf32.tf32.f32 "
        "{%0,%1,%2,%3}, {%4,%5,%6,%7}, {%8,%9}, {%0,%1,%2,%3};"
        : "+f"(d[0]), "+f"(d[1]), "+f"(d[2]), "+f"(d[3])
        : "r"(a[0]), "r"(a[1]), "r"(a[2]), "r"(a[3]), "r"(b[0]), "r"(b[1]));
}

// ---------------- tf32 mma GEMM: C = A[M,K] @ BT[N,K]^T ---------------------
// 128x128 CTA tile, 8 warps (2x4), warp tile 64x32, K-chunk 32.
// Software pipeline: register prefetch of chunk kt+1 + double-buffered SMEM.
enum { EPI_QKV = 0, EPI_BIAS_RESID = 1, EPI_BIAS_RELU = 2, EPI_SCORES = 3 };

#define GM_AS_STRIDE 36
#define GM_TILE_F    (128 * GM_AS_STRIDE)            // floats per tile
#define GM_BUF_F     (2 * GM_TILE_F)                 // A + B per stage
#define GM_SMEM_B    (2 * GM_BUF_F * 4)              // 2 stages, bytes = 73728

template<int EPI>
__global__ __launch_bounds__(256) void gemm_mma(
    const float* __restrict__ A, const float* __restrict__ BT,
    float* __restrict__ C, int N, int K,
    long long sAz, long long sBz, long long sCz,
    const float* __restrict__ bias, const float* __restrict__ resid,
    float* __restrict__ qp, float* __restrict__ kp, float* __restrict__ vp)
{
    extern __shared__ float smem[];

    const float* Ab = A  + (size_t)blockIdx.z * sAz;
    const float* Bb = BT + (size_t)blockIdx.z * sBz;
    float*       Cb = C  + (size_t)blockIdx.z * sCz;

    const int tid  = threadIdx.x;
    const int wid  = tid >> 5;
    const int lane = tid & 31;
    const int g    = lane >> 2;
    const int t4   = lane & 3;
    const int wm   = wid >> 2;          // 0..1  (64-row slab)
    const int wn   = wid & 3;           // 0..3  (32-col slab)
    const int tileM = blockIdx.y * 128;
    const int tileN = blockIdx.x * 128;

    const int ldr = tid >> 3;           // 0..31 (row group base; r = ldr used via idx)
    (void)ldr;

    float acc[4][4][4];
#pragma unroll
    for (int i = 0; i < 4; i++)
#pragma unroll
        for (int j = 0; j < 4; j++)
#pragma unroll
            for (int c = 0; c < 4; c++) acc[i][j][c] = 0.f;

    float4 pa[4], pb[4];

    // prefetch chunk 0
#pragma unroll
    for (int i = 0; i < 4; i++) {
        const int idx = i * 256 + tid;
        const int r   = idx >> 3;
        const int c4  = (idx & 7) * 4;
        pa[i] = *(const float4*)(Ab + (size_t)(tileM + r) * K + c4);
        pb[i] = *(const float4*)(Bb + (size_t)(tileN + r) * K + c4);
    }
    // store chunk 0 into stage 0
    {
        float* As = smem;
        float* Bs = smem + GM_TILE_F;
#pragma unroll
        for (int i = 0; i < 4; i++) {
            const int idx = i * 256 + tid;
            const int r   = idx >> 3;
            const int c4  = (idx & 7) * 4;
            float* ar = As + r * GM_AS_STRIDE + c4;
            ar[0] = f2tf32(pa[i].x); ar[1] = f2tf32(pa[i].y);
            ar[2] = f2tf32(pa[i].z); ar[3] = f2tf32(pa[i].w);
            float* br = Bs + r * GM_AS_STRIDE + c4;
            br[0] = f2tf32(pb[i].x); br[1] = f2tf32(pb[i].y);
            br[2] = f2tf32(pb[i].z); br[3] = f2tf32(pb[i].w);
        }
    }
    __syncthreads();

    const int KT = K >> 5;
    for (int kt = 0; kt < KT; kt++) {
        // issue global loads for chunk kt+1 (latency hidden by MMAs below)
        const bool more = (kt + 1) < KT;
        if (more) {
            const int k0 = (kt + 1) << 5;
#pragma unroll
            for (int i = 0; i < 4; i++) {
                const int idx = i * 256 + tid;
                const int r   = idx >> 3;
                const int c4  = (idx & 7) * 4;
                pa[i] = *(const float4*)(Ab + (size_t)(tileM + r) * K + k0 + c4);
                pb[i] = *(const float4*)(Bb + (size_t)(tileN + r) * K + k0 + c4);
            }
        }

        // compute on stage kt&1
        {
            const float* As = smem + (kt & 1) * GM_BUF_F;
            const float* Bs = As + GM_TILE_F;
#pragma unroll
            for (int ks = 0; ks < 4; ks++) {
                const int k = ks * 8;
                uint32_t af[4][4], bf[4][2];
#pragma unroll
                for (int mi = 0; mi < 4; mi++) {
                    const int rb = wm * 64 + mi * 16;
                    af[mi][0] = __float_as_uint(As[(rb + g    ) * GM_AS_STRIDE + k + t4    ]);
                    af[mi][1] = __float_as_uint(As[(rb + g + 8) * GM_AS_STRIDE + k + t4    ]);
                    af[mi][2] = __float_as_uint(As[(rb + g    ) * GM_AS_STRIDE + k + t4 + 4]);
                    af[mi][3] = __float_as_uint(As[(rb + g + 8) * GM_AS_STRIDE + k + t4 + 4]);
                }
#pragma unroll
                for (int ni = 0; ni < 4; ni++) {
                    const int nb = wn * 32 + ni * 8;
                    bf[ni][0] = __float_as_uint(Bs[(nb + g) * GM_AS_STRIDE + k + t4    ]);
                    bf[ni][1] = __float_as_uint(Bs[(nb + g) * GM_AS_STRIDE + k + t4 + 4]);
                }
#pragma unroll
                for (int mi = 0; mi < 4; mi++)
#pragma unroll
                    for (int ni = 0; ni < 4; ni++)
                        mma_tf32(acc[mi][ni], af[mi], bf[ni]);
            }
        }

        // store chunk kt+1 into the other stage
        if (more) {
            float* As = smem + ((kt + 1) & 1) * GM_BUF_F;
            float* Bs = As + GM_TILE_F;
#pragma unroll
            for (int i = 0; i < 4; i++) {
                const int idx = i * 256 + tid;
                const int r   = idx >> 3;
                const int c4  = (idx & 7) * 4;
                float* ar = As + r * GM_AS_STRIDE + c4;
                ar[0] = f2tf32(pa[i].x); ar[1] = f2tf32(pa[i].y);
                ar[2] = f2tf32(pa[i].z); ar[3] = f2tf32(pa[i].w);
                float* br = Bs + r * GM_AS_STRIDE + c4;
                br[0] = f2tf32(pb[i].x); br[1] = f2tf32(pb[i].y);
                br[2] = f2tf32(pb[i].z); br[3] = f2tf32(pb[i].w);
            }
            __syncthreads();
        }
    }

    // epilogue
#pragma unroll
    for (int mi = 0; mi < 4; mi++) {
#pragma unroll
        for (int half = 0; half < 2; half++) {
            const int m = tileM + wm * 64 + mi * 16 + g + half * 8;
#pragma unroll
            for (int ni = 0; ni < 4; ni++) {
                const int n = tileN + wn * 32 + ni * 8 + t4 * 2;
                float v0 = acc[mi][ni][half * 2 + 0];
                float v1 = acc[mi][ni][half * 2 + 1];
                if (EPI == EPI_SCORES) {
                    float2 o = make_float2(v0 * 0.125f, v1 * 0.125f);
                    *(float2*)(Cb + (size_t)m * N + n) = o;
                } else if (EPI == EPI_QKV) {
                    const int b = m >> 10, l = m & 1023;
                    const int which = n >> 10, rem = n & 1023;
                    const int h = rem >> 6, d = rem & 63;
                    float* dst = (which == 0) ? qp : (which == 1) ? kp : vp;
                    float2 o = make_float2(v0, v1);
                    *(float2*)(dst + ((size_t)((b * NH + h) * LSEQ + l)) * DH + d) = o;
                } else {
                    const size_t idx = (size_t)m * N + n;
                    const float2 bb = *(const float2*)(bias + n);
                    v0 += bb.x; v1 += bb.y;
                    if (EPI == EPI_BIAS_RESID) {
                        const float2 rr = *(const float2*)(resid + idx);
                        v0 += rr.x; v1 += rr.y;
                    } else {
                        v0 = fmaxf(v0, 0.f); v1 = fmaxf(v1, 0.f);
                    }
                    *(float2*)(Cb + idx) = make_float2(v0, v1);
                }
            }
        }
    }
}

// ---------------- P @ V via mma: tile 256x64, warps 4x2, pipelined ----------
#define AV_P_STRIDE 36
#define AV_V_STRIDE 68
#define AV_P_F  (256 * AV_P_STRIDE)
#define AV_V_F  (32 * AV_V_STRIDE)
#define AV_BUF_F (AV_P_F + AV_V_F)
#define AV_SMEM_B (2 * AV_BUF_F * 4)     // 91136 bytes

__global__ __launch_bounds__(256) void attn_av_mma(
    const float* __restrict__ P, const float* __restrict__ V,
    float* __restrict__ H)
{
    extern __shared__ float smem[];

    const int z = blockIdx.y;
    const int b = z >> 4, h = z & 15;
    const float* p = P + (size_t)z * LSEQ * LSEQ;
    const float* v = V + (size_t)z * LSEQ * DH;

    const int tid  = threadIdx.x;
    const int wid  = tid >> 5;
    const int lane = tid & 31;
    const int g    = lane >> 2;
    const int t4   = lane & 3;
    const int wm   = wid >> 1;          // 0..3 (64-row slab)
    const int wn   = wid & 1;           // 0..1 (32-col slab)
    const int tileM = blockIdx.x * 256;

    float acc[4][4][4];
#pragma unroll
    for (int i = 0; i < 4; i++)
#pragma unroll
        for (int j = 0; j < 4; j++)
#pragma unroll
            for (int c = 0; c < 4; c++) acc[i][j][c] = 0.f;

    float4 pp[8], pv[2];

#pragma unroll
    for (int i = 0; i < 8; i++) {
        const int idx = i * 256 + tid;
        const int r   = idx >> 3;
        const int c4  = (idx & 7) * 4;
        pp[i] = *(const float4*)(p + (size_t)(tileM + r) * LSEQ + c4);
    }
#pragma unroll
    for (int i = 0; i < 2; i++) {
        const int idx = i * 256 + tid;
        const int r   = idx >> 4;
        const int c4  = (idx & 15) * 4;
        pv[i] = *(const float4*)(v + (size_t)r * DH + c4);
    }
    {
        float* Ps = smem;
        float* Vs = smem + AV_P_F;
#pragma unroll
        for (int i = 0; i < 8; i++) {
            const int idx = i * 256 + tid;
            const int r   = idx >> 3;
            const int c4  = (idx & 7) * 4;
            float* pr = Ps + r * AV_P_STRIDE + c4;
            pr[0] = f2tf32(pp[i].x); pr[1] = f2tf32(pp[i].y);
            pr[2] = f2tf32(pp[i].z); pr[3] = f2tf32(pp[i].w);
        }
#pragma unroll
        for (int i = 0; i < 2; i++) {
            const int idx = i * 256 + tid;
            const int r   = idx >> 4;
            const int c4  = (idx & 15) * 4;
            float* vr = Vs + r * AV_V_STRIDE + c4;
            vr[0] = f2tf32(pv[i].x); vr[1] = f2tf32(pv[i].y);
            vr[2] = f2tf32(pv[i].z); vr[3] = f2tf32(pv[i].w);
        }
    }
    __syncthreads();

    const int KT = LSEQ / 32;
    for (int kt = 0; kt < KT; kt++) {
        const bool more = (kt + 1) < KT;
        if (more) {
            const int k0 = (kt + 1) * 32;
#pragma unroll
            for (int i = 0; i < 8; i++) {
                const int idx = i * 256 + tid;
                const int r   = idx >> 3;
                const int c4  = (idx & 7) * 4;
                pp[i] = *(const float4*)(p + (size_t)(tileM + r) * LSEQ + k0 + c4);
            }
#pragma unroll
            for (int i = 0; i < 2; i++) {
                const int idx = i * 256 + tid;
                const int r   = idx >> 4;
                const int c4  = (idx & 15) * 4;
                pv[i] = *(const float4*)(v + (size_t)(k0 + r) * DH + c4);
            }
        }

        {
            const float* Ps = smem + (kt & 1) * AV_BUF_F;
            const float* Vs = Ps + AV_P_F;
#pragma unroll
            for (int ks = 0; ks < 4; ks++) {
                const int k = ks * 8;
                uint32_t af[4][4], bf[4][2];
#pragma unroll
                for (int mi = 0; mi < 4; mi++) {
                    const int rb = wm * 64 + mi * 16;
                    af[mi][0] = __float_as_uint(Ps[(rb + g    ) * AV_P_STRIDE + k + t4    ]);
                    af[mi][1] = __float_as_uint(Ps[(rb + g + 8) * AV_P_STRIDE + k + t4    ]);
                    af[mi][2] = __float_as_uint(Ps[(rb + g    ) * AV_P_STRIDE + k + t4 + 4]);
                    af[mi][3] = __float_as_uint(Ps[(rb + g + 8) * AV_P_STRIDE + k + t4 + 4]);
                }
#pragma unroll
                for (int ni = 0; ni < 4; ni++) {
                    const int nb = wn * 32 + ni * 8;
                    bf[ni][0] = __float_as_uint(Vs[(k + t4    ) * AV_V_STRIDE + nb + g]);
                    bf[ni][1] = __float_as_uint(Vs[(k + t4 + 4) * AV_V_STRIDE + nb + g]);
                }
#pragma unroll
                for (int mi = 0; mi < 4; mi++)
#pragma unroll
                    for (int ni = 0; ni < 4; ni++)
                        mma_tf32(acc[mi][ni], af[mi], bf[ni]);
            }
        }

        if (more) {
            float* Ps = smem + ((kt + 1) & 1) * AV_BUF_F;
            float* Vs = Ps + AV_P_F;
#pragma unroll
            for (int i = 0; i < 8; i++) {
                const int idx = i * 256 + tid;
                const int r   = idx >> 3;
                const int c4  = (idx & 7) * 4;
                float* pr = Ps + r * AV_P_STRIDE + c4;
                pr[0] = f2tf32(pp[i].x); pr[1] = f2tf32(pp[i].y);
                pr[2] = f2tf32(pp[i].z); pr[3] = f2tf32(pp[i].w);
            }
#pragma unroll
            for (int i = 0; i < 2; i++) {
                const int idx = i * 256 + tid;
                const int r   = idx >> 4;
                const int c4  = (idx & 15) * 4;
                float* vr = Vs + r * AV_V_STRIDE + c4;
                vr[0] = f2tf32(pv[i].x); vr[1] = f2tf32(pv[i].y);
                vr[2] = f2tf32(pv[i].z); vr[3] = f2tf32(pv[i].w);
            }
            __syncthreads();
        }
    }

#pragma unroll
    for (int mi = 0; mi < 4; mi++) {
#pragma unroll
        for (int half = 0; half < 2; half++) {
            const int l = tileM + wm * 64 + mi * 16 + g + half * 8;
#pragma unroll
            for (int ni = 0; ni < 4; ni++) {
                const int d = wn * 32 + ni * 8 + t4 * 2;
                float2 o = make_float2(acc[mi][ni][half * 2 + 0],
                                       acc[mi][ni][half * 2 + 1]);
                *(float2*)(H + (size_t)(b * LSEQ + l) * D_MODEL + h * DH + d) = o;
            }
        }
    }
}

// ---------------- weight transpose: out[n][k] = in[k][n] --------------------
__global__ __launch_bounds__(256) void transpose_k(
    const float* __restrict__ in, float* __restrict__ out, int K, int N)
{
    __shared__ float t[32][33];
    const int bn = blockIdx.x * 32, bk = blockIdx.y * 32;
    const int tx = threadIdx.x, ty = threadIdx.y;
#pragma unroll
    for (int i = ty; i < 32; i += 8)
        t[i][tx] = in[(size_t)(bk + i) * N + bn + tx];
    __syncthreads();
#pragma unroll
    for (int i = ty; i < 32; i += 8)
        out[(size_t)(bn + i) * K + bk + tx] = t[tx][i];
}

// ---------------- masked row softmax (in place) -----------------------------
__global__ __launch_bounds__(256) void softmax_mask(
    float* __restrict__ S, const int* __restrict__ mask)
{
    __shared__ float red[8];
    const size_t r = blockIdx.x;
    const int b = (int)(r >> 14);
    float* row = S + r * LSEQ;
    const int* mrow = mask + (size_t)b * LSEQ;
    const int tid = threadIdx.x;

    float4 v = *(const float4*)(row + tid * 4);
    int4  mv = *(const int4*)(mrow + tid * 4);
    if (mv.x == 0) v.x = -1e10f;
    if (mv.y == 0) v.y = -1e10f;
    if (mv.z == 0) v.z = -1e10f;
    if (mv.w == 0) v.w = -1e10f;

    float mx = fmaxf(fmaxf(v.x, v.y), fmaxf(v.z, v.w));
#pragma unroll
    for (int o = 16; o > 0; o >>= 1) mx = fmaxf(mx, __shfl_xor_sync(0xffffffffu, mx, o));
    if ((tid & 31) == 0) red[tid >> 5] = mx;
    __syncthreads();
    mx = red[0];
#pragma unroll
    for (int i = 1; i < 8; i++) mx = fmaxf(mx, red[i]);
    __syncthreads();

    v.x = __expf(v.x - mx); v.y = __expf(v.y - mx);
    v.z = __expf(v.z - mx); v.w = __expf(v.w - mx);
    float sm = v.x + v.y + v.z + v.w;
#pragma unroll
    for (int o = 16; o > 0; o >>= 1) sm += __shfl_xor_sync(0xffffffffu, sm, o);
    if ((tid & 31) == 0) red[tid >> 5] = sm;
    __syncthreads();
    sm = 0.f;
#pragma unroll
    for (int i = 0; i < 8; i++) sm += red[i];
    float inv = 1.f / sm;
    v.x *= inv; v.y *= inv; v.z *= inv; v.w *= inv;
    *(float4*)(row + tid * 4) = v;
}

// ---------------- layernorm --------------------------------------------------
__global__ __launch_bounds__(256) void layernorm(
    const float* __restrict__ X, const float* __restrict__ g,
    const float* __restrict__ be, float* __restrict__ O)
{
    __shared__ float red[8];
    const int r = blockIdx.x;
    const int tid = threadIdx.x;
    const float4 v = *(const float4*)(X + (size_t)r * D_MODEL + tid * 4);

    float s = v.x + v.y + v.z + v.w;
#pragma unroll
    for (int o = 16; o > 0; o >>= 1) s += __shfl_xor_sync(0xffffffffu, s, o);
    if ((tid & 31) == 0) red[tid >> 5] = s;
    __syncthreads();
    s = 0.f;
#pragma unroll
    for (int i = 0; i < 8; i++) s += red[i];
    const float mu = s * (1.f / D_MODEL);
    __syncthreads();

    float dx = v.x - mu, dy = v.y - mu, dz = v.z - mu, dw = v.w - mu;
    float sq = dx * dx + dy * dy + dz * dz + dw * dw;
#pragma unroll
    for (int o = 16; o > 0; o >>= 1) sq += __shfl_xor_sync(0xffffffffu, sq, o);
    if ((tid & 31) == 0) red[tid >> 5] = sq;
    __syncthreads();
    sq = 0.f;
#pragma unroll
    for (int i = 0; i < 8; i++) sq += red[i];
    const float rs = rsqrtf(sq * (1.f / D_MODEL) + 1e-5f);

    const float4 gg = *(const float4*)(g + tid * 4);
    const float4 bb = *(const float4*)(be + tid * 4);
    float4 o;
    o.x = dx * rs * gg.x + bb.x;
    o.y = dy * rs * gg.y + bb.y;
    o.z = dz * rs * gg.z + bb.z;
    o.w = dw * rs * gg.w + bb.w;
    *(float4*)(O + (size_t)r * D_MODEL + tid * 4) = o;
}

// ---------------- launch -----------------------------------------------------
extern "C" void kernel_launch(void* const* d_in, const int* in_sizes, int n_in,
                              void* d_out, int out_size)
{
    const float* x   = (const float*)d_in[0];
    const int*   msk = (const int*)d_in[1];
    const float* Wq  = (const float*)d_in[2];
    const float* Wk  = (const float*)d_in[3];
    const float* Wv  = (const float*)d_in[4];
    const float* Wp  = (const float*)d_in[5];
    const float* bp  = (const float*)d_in[6];
    const float* W1  = (const float*)d_in[7];
    const float* b1  = (const float*)d_in[8];
    const float* W2  = (const float*)d_in[9];
    const float* b2  = (const float*)d_in[10];
    const float* g1  = (const float*)d_in[11];
    const float* be1 = (const float*)d_in[12];
    const float* g2  = (const float*)d_in[13];
    const float* be2 = (const float*)d_in[14];
    float* out = (float*)d_out;

    float *q, *k, *v, *sc, *hd, *tmp, *h, *ff, *wtqkv, *wtp, *wt1, *wt2;
    cudaGetSymbolAddress((void**)&q,     g_q);
    cudaGetSymbolAddress((void**)&k,     g_k);
    cudaGetSymbolAddress((void**)&v,     g_v);
    cudaGetSymbolAddress((void**)&sc,    g_scores);
    cudaGetSymbolAddress((void**)&hd,    g_heads);
    cudaGetSymbolAddress((void**)&tmp,   g_tmp);
    cudaGetSymbolAddress((void**)&h,     g_h);
    cudaGetSymbolAddress((void**)&ff,    g_ff);
    cudaGetSymbolAddress((void**)&wtqkv, g_wtqkv);
    cudaGetSymbolAddress((void**)&wtp,   g_wtp);
    cudaGetSymbolAddress((void**)&wt1,   g_wt1);
    cudaGetSymbolAddress((void**)&wt2,   g_wt2);

    static bool attr_done = false;
    if (!attr_done) {
        cudaFuncSetAttribute(gemm_mma<EPI_QKV>,
                             cudaFuncAttributeMaxDynamicSharedMemorySize, GM_SMEM_B);
        cudaFuncSetAttribute(gemm_mma<EPI_BIAS_RESID>,
                             cudaFuncAttributeMaxDynamicSharedMemorySize, GM_SMEM_B);
        cudaFuncSetAttribute(gemm_mma<EPI_BIAS_RELU>,
                             cudaFuncAttributeMaxDynamicSharedMemorySize, GM_SMEM_B);
        cudaFuncSetAttribute(gemm_mma<EPI_SCORES>,
                             cudaFuncAttributeMaxDynamicSharedMemorySize, GM_SMEM_B);
        cudaFuncSetAttribute(attn_av_mma,
                             cudaFuncAttributeMaxDynamicSharedMemorySize, AV_SMEM_B);
        attr_done = true;
    }

    dim3 blk(256);
    dim3 tb(32, 8);

    // weight transposes -> (N,K) layouts
    transpose_k<<<dim3(32, 32), tb>>>(Wq, wtqkv + 0 * 1024 * 1024, D_MODEL, D_MODEL);
    transpose_k<<<dim3(32, 32), tb>>>(Wk, wtqkv + 1 * 1024 * 1024, D_MODEL, D_MODEL);
    transpose_k<<<dim3(32, 32), tb>>>(Wv, wtqkv + 2 * 1024 * 1024, D_MODEL, D_MODEL);
    transpose_k<<<dim3(32, 32), tb>>>(Wp, wtp, D_MODEL, D_MODEL);
    transpose_k<<<dim3(128, 32), tb>>>(W1, wt1, D_MODEL, DFF);   // 1024x4096 -> 4096x1024
    transpose_k<<<dim3(32, 128), tb>>>(W2, wt2, DFF, D_MODEL);   // 4096x1024 -> 1024x4096

    // fused QKV projection (M=4096, N=3072, K=1024), scatter to head layout
    gemm_mma<EPI_QKV><<<dim3(24, 32, 1), blk, GM_SMEM_B>>>(
        x, wtqkv, nullptr, 3072, 1024, 0, 0, 0, nullptr, nullptr, q, k, v);

    // scores = QK^T / 8 (batched per head, K=64)
    gemm_mma<EPI_SCORES><<<dim3(8, 8, ZHEADS), blk, GM_SMEM_B>>>(
        q, k, sc, LSEQ, DH,
        (long long)LSEQ * DH, (long long)LSEQ * DH, (long long)LSEQ * LSEQ,
        nullptr, nullptr, nullptr, nullptr, nullptr);

    softmax_mask<<<ZHEADS * LSEQ, blk>>>(sc, msk);

    // heads = P @ V (per head, tile 256x64)
    attn_av_mma<<<dim3(4, ZHEADS), blk, AV_SMEM_B>>>(sc, v, hd);

    // proj + bias + residual, LN1
    gemm_mma<EPI_BIAS_RESID><<<dim3(8, 32, 1), blk, GM_SMEM_B>>>(
        hd, wtp, tmp, 1024, 1024, 0, 0, 0, bp, x, nullptr, nullptr, nullptr);
    layernorm<<<MROWS, blk>>>(tmp, g1, be1, h);

    // FF1 (ReLU), FF2 + bias + residual, LN2
    gemm_mma<EPI_BIAS_RELU><<<dim3(32, 32, 1), blk, GM_SMEM_B>>>(
        h, wt1, ff, 4096, 1024, 0, 0, 0, b1, nullptr, nullptr, nullptr, nullptr);
    gemm_mma<EPI_BIAS_RESID><<<dim3(8, 32, 1), blk, GM_SMEM_B>>>(
        ff, wt2, tmp, 1024, 4096, 0, 0, 0, b2, h, nullptr, nullptr, nullptr);
    layernorm<<<MROWS, blk>>>(tmp, g2, be2, out);
}

// round 6
// speedup vs baseline: 4.7551x; 1.1121x over previous
#include <cuda_runtime.h>
#include <cstdint>
#include <math.h>

#define D_MODEL 1024
#define NH      16
#define DH      64
#define DFF     4096
#define BATCH   4
#define LSEQ    1024
#define MROWS   (BATCH*LSEQ)       // 4096
#define ZHEADS  (BATCH*NH)         // 64

// ---------------- scratch (device globals; no runtime allocation) ----------
__device__ float g_q[(size_t)ZHEADS*LSEQ*DH];          // (b,h,l,d)
__device__ float g_k[(size_t)ZHEADS*LSEQ*DH];
__device__ float g_v[(size_t)ZHEADS*LSEQ*DH];
__device__ float g_heads[(size_t)MROWS*D_MODEL];
__device__ float g_tmp[(size_t)MROWS*D_MODEL];
__device__ float g_h[(size_t)MROWS*D_MODEL];
__device__ float g_ff[(size_t)MROWS*DFF];
__device__ float g_wtqkv[(size_t)3*D_MODEL*D_MODEL];   // [3*1024][1024] (N,K)
__device__ float g_wtp[(size_t)D_MODEL*D_MODEL];
__device__ float g_wt1[(size_t)DFF*D_MODEL];           // [4096][1024]
__device__ float g_wt2[(size_t)D_MODEL*DFF];           // [1024][4096]

// ---------------- helpers ----------------------------------------------------
__device__ __forceinline__ float f2tf32(float f) {
    uint32_t r;
    asm("cvt.rna.tf32.f32 %0, %1;" : "=r"(r) : "f"(f));
    return __uint_as_float(r);
}
__device__ __forceinline__ void mma_tf32(float* d, const uint32_t* a,
                                         const uint32_t* b) {
    asm volatile(
        "mma.sync.aligned.m16n8k8.row.col.f32.tf32.tf32.f32 "
        "{%0,%1,%2,%3}, {%4,%5,%6,%7}, {%8,%9}, {%0,%1,%2,%3};"
        : "+f"(d[0]), "+f"(d[1]), "+f"(d[2]), "+f"(d[3])
        : "r"(a[0]), "r"(a[1]), "r"(a[2]), "r"(a[3]), "r"(b[0]), "r"(b[1]));
}

// ---------------- tf32 mma GEMM: C = A[M,K] @ BT[N,K]^T ---------------------
// 128x128 CTA tile, 8 warps (2x4), warp tile 64x32, K-chunk 32.
// Software pipeline: register prefetch of chunk kt+1 + double-buffered SMEM.
enum { EPI_QKV = 0, EPI_BIAS_RESID = 1, EPI_BIAS_RELU = 2 };

#define GM_AS_STRIDE 36
#define GM_TILE_F    (128 * GM_AS_STRIDE)            // floats per tile
#define GM_BUF_F     (2 * GM_TILE_F)                 // A + B per stage
#define GM_SMEM_B    (2 * GM_BUF_F * 4)              // 2 stages, bytes = 73728

template<int EPI>
__global__ __launch_bounds__(256) void gemm_mma(
    const float* __restrict__ A, const float* __restrict__ BT,
    float* __restrict__ C, int N, int K,
    const float* __restrict__ bias, const float* __restrict__ resid,
    float* __restrict__ qp, float* __restrict__ kp, float* __restrict__ vp)
{
    extern __shared__ float smem[];

    const float* Ab = A;
    const float* Bb = BT;
    float*       Cb = C;

    const int tid  = threadIdx.x;
    const int wid  = tid >> 5;
    const int lane = tid & 31;
    const int g    = lane >> 2;
    const int t4   = lane & 3;
    const int wm   = wid >> 2;          // 0..1  (64-row slab)
    const int wn   = wid & 3;           // 0..3  (32-col slab)
    const int tileM = blockIdx.y * 128;
    const int tileN = blockIdx.x * 128;

    float acc[4][4][4];
#pragma unroll
    for (int i = 0; i < 4; i++)
#pragma unroll
        for (int j = 0; j < 4; j++)
#pragma unroll
            for (int c = 0; c < 4; c++) acc[i][j][c] = 0.f;

    float4 pa[4], pb[4];

    // prefetch chunk 0
#pragma unroll
    for (int i = 0; i < 4; i++) {
        const int idx = i * 256 + tid;
        const int r   = idx >> 3;
        const int c4  = (idx & 7) * 4;
        pa[i] = *(const float4*)(Ab + (size_t)(tileM + r) * K + c4);
        pb[i] = *(const float4*)(Bb + (size_t)(tileN + r) * K + c4);
    }
    {
        float* As = smem;
        float* Bs = smem + GM_TILE_F;
#pragma unroll
        for (int i = 0; i < 4; i++) {
            const int idx = i * 256 + tid;
            const int r   = idx >> 3;
            const int c4  = (idx & 7) * 4;
            float* ar = As + r * GM_AS_STRIDE + c4;
            ar[0] = f2tf32(pa[i].x); ar[1] = f2tf32(pa[i].y);
            ar[2] = f2tf32(pa[i].z); ar[3] = f2tf32(pa[i].w);
            float* br = Bs + r * GM_AS_STRIDE + c4;
            br[0] = f2tf32(pb[i].x); br[1] = f2tf32(pb[i].y);
            br[2] = f2tf32(pb[i].z); br[3] = f2tf32(pb[i].w);
        }
    }
    __syncthreads();

    const int KT = K >> 5;
    for (int kt = 0; kt < KT; kt++) {
        const bool more = (kt + 1) < KT;
        if (more) {
            const int k0 = (kt + 1) << 5;
#pragma unroll
            for (int i = 0; i < 4; i++) {
                const int idx = i * 256 + tid;
                const int r   = idx >> 3;
                const int c4  = (idx & 7) * 4;
                pa[i] = *(const float4*)(Ab + (size_t)(tileM + r) * K + k0 + c4);
                pb[i] = *(const float4*)(Bb + (size_t)(tileN + r) * K + k0 + c4);
            }
        }

        {
            const float* As = smem + (kt & 1) * GM_BUF_F;
            const float* Bs = As + GM_TILE_F;
#pragma unroll
            for (int ks = 0; ks < 4; ks++) {
                const int k = ks * 8;
                uint32_t af[4][4], bf[4][2];
#pragma unroll
                for (int mi = 0; mi < 4; mi++) {
                    const int rb = wm * 64 + mi * 16;
                    af[mi][0] = __float_as_uint(As[(rb + g    ) * GM_AS_STRIDE + k + t4    ]);
                    af[mi][1] = __float_as_uint(As[(rb + g + 8) * GM_AS_STRIDE + k + t4    ]);
                    af[mi][2] = __float_as_uint(As[(rb + g    ) * GM_AS_STRIDE + k + t4 + 4]);
                    af[mi][3] = __float_as_uint(As[(rb + g + 8) * GM_AS_STRIDE + k + t4 + 4]);
                }
#pragma unroll
                for (int ni = 0; ni < 4; ni++) {
                    const int nb = wn * 32 + ni * 8;
                    bf[ni][0] = __float_as_uint(Bs[(nb + g) * GM_AS_STRIDE + k + t4    ]);
                    bf[ni][1] = __float_as_uint(Bs[(nb + g) * GM_AS_STRIDE + k + t4 + 4]);
                }
#pragma unroll
                for (int mi = 0; mi < 4; mi++)
#pragma unroll
                    for (int ni = 0; ni < 4; ni++)
                        mma_tf32(acc[mi][ni], af[mi], bf[ni]);
            }
        }

        if (more) {
            float* As = smem + ((kt + 1) & 1) * GM_BUF_F;
            float* Bs = As + GM_TILE_F;
#pragma unroll
            for (int i = 0; i < 4; i++) {
                const int idx = i * 256 + tid;
                const int r   = idx >> 3;
                const int c4  = (idx & 7) * 4;
                float* ar = As + r * GM_AS_STRIDE + c4;
                ar[0] = f2tf32(pa[i].x); ar[1] = f2tf32(pa[i].y);
                ar[2] = f2tf32(pa[i].z); ar[3] = f2tf32(pa[i].w);
                float* br = Bs + r * GM_AS_STRIDE + c4;
                br[0] = f2tf32(pb[i].x); br[1] = f2tf32(pb[i].y);
                br[2] = f2tf32(pb[i].z); br[3] = f2tf32(pb[i].w);
            }
            __syncthreads();
        }
    }

    // epilogue
#pragma unroll
    for (int mi = 0; mi < 4; mi++) {
#pragma unroll
        for (int half = 0; half < 2; half++) {
            const int m = tileM + wm * 64 + mi * 16 + g + half * 8;
#pragma unroll
            for (int ni = 0; ni < 4; ni++) {
                const int n = tileN + wn * 32 + ni * 8 + t4 * 2;
                float v0 = acc[mi][ni][half * 2 + 0];
                float v1 = acc[mi][ni][half * 2 + 1];
                if (EPI == EPI_QKV) {
                    const int b = m >> 10, l = m & 1023;
                    const int which = n >> 10, rem = n & 1023;
                    const int h = rem >> 6, d = rem & 63;
                    float* dst = (which == 0) ? qp : (which == 1) ? kp : vp;
                    float2 o = make_float2(v0, v1);
                    *(float2*)(dst + ((size_t)((b * NH + h) * LSEQ + l)) * DH + d) = o;
                } else {
                    const size_t idx = (size_t)m * N + n;
                    const float2 bb = *(const float2*)(bias + n);
                    v0 += bb.x; v1 += bb.y;
                    if (EPI == EPI_BIAS_RESID) {
                        const float2 rr = *(const float2*)(resid + idx);
                        v0 += rr.x; v1 += rr.y;
                    } else {
                        v0 = fmaxf(v0, 0.f); v1 = fmaxf(v1, 0.f);
                    }
                    *(float2*)(Cb + idx) = make_float2(v0, v1);
                }
            }
        }
    }
}

// ---------------- fused flash attention --------------------------------------
// Per (head z, 128-row Q tile): S = QK^T/8 (masked) -> online softmax -> O += P V.
// 8 warps, each owns 16 Q rows. P goes through SMEM per-warp (syncwarp only).
#define FA_QK_S 68
#define FA_V_S  72
#define FA_P_S  132
#define FA_Q_OFF 0
#define FA_K_OFF (FA_Q_OFF + 128 * FA_QK_S)   // 8704
#define FA_V_OFF (FA_K_OFF + 128 * FA_QK_S)   // 17408
#define FA_P_OFF (FA_V_OFF + 128 * FA_V_S)    // 26624
#define FA_M_OFF (FA_P_OFF + 128 * FA_P_S)    // 43520
#define FA_SMEM_B ((FA_M_OFF + 128) * 4)      // 174592 bytes

__global__ __launch_bounds__(256) void flash_attn(
    const float* __restrict__ Qg, const float* __restrict__ Kg,
    const float* __restrict__ Vg, const int* __restrict__ mask,
    float* __restrict__ H)
{
    extern __shared__ float smem[];
    float* Qs = smem + FA_Q_OFF;
    float* Ks = smem + FA_K_OFF;
    float* Vs = smem + FA_V_OFF;
    float* Ps = smem + FA_P_OFF;
    int*   Ms = (int*)(smem + FA_M_OFF);

    const int z = blockIdx.y;
    const int b = z >> 4, h = z & 15;
    const float* q  = Qg + (size_t)z * LSEQ * DH;
    const float* kp = Kg + (size_t)z * LSEQ * DH;
    const float* vp = Vg + (size_t)z * LSEQ * DH;
    const int* mb = mask + (size_t)b * LSEQ;
    const int tileQ = blockIdx.x * 128;

    const int tid  = threadIdx.x;
    const int wid  = tid >> 5;
    const int lane = tid & 31;
    const int g    = lane >> 2;
    const int t4   = lane & 3;
    const int rb   = wid * 16;

    // Q tile -> SMEM (tf32)
#pragma unroll
    for (int i = 0; i < 8; i++) {
        const int idx = i * 256 + tid;
        const int r   = idx >> 4;
        const int c4  = (idx & 15) * 4;
        float4 v4 = *(const float4*)(q + (size_t)(tileQ + r) * DH + c4);
        float* dst = Qs + r * FA_QK_S + c4;
        dst[0] = f2tf32(v4.x); dst[1] = f2tf32(v4.y);
        dst[2] = f2tf32(v4.z); dst[3] = f2tf32(v4.w);
    }

    float mrow0 = -1e30f, mrow1 = -1e30f;
    float lrow0 = 0.f, lrow1 = 0.f;
    float oacc[8][4];
#pragma unroll
    for (int i = 0; i < 8; i++)
#pragma unroll
        for (int c = 0; c < 4; c++) oacc[i][c] = 0.f;

    for (int kt = 0; kt < 8; kt++) {
        const int k0 = kt * 128;
        __syncthreads();   // all warps done with previous Ks/Vs
#pragma unroll
        for (int i = 0; i < 8; i++) {
            const int idx = i * 256 + tid;
            const int r   = idx >> 4;
            const int c4  = (idx & 15) * 4;
            float4 kv = *(const float4*)(kp + (size_t)(k0 + r) * DH + c4);
            float* kd = Ks + r * FA_QK_S + c4;
            kd[0] = f2tf32(kv.x); kd[1] = f2tf32(kv.y);
            kd[2] = f2tf32(kv.z); kd[3] = f2tf32(kv.w);
            float4 vv = *(const float4*)(vp + (size_t)(k0 + r) * DH + c4);
            float* vd = Vs + r * FA_V_S + c4;
            vd[0] = f2tf32(vv.x); vd[1] = f2tf32(vv.y);
            vd[2] = f2tf32(vv.z); vd[3] = f2tf32(vv.w);
        }
        if (tid < 128) Ms[tid] = mb[k0 + tid];
        __syncthreads();

        // S = Q K^T  (warp rows rb..rb+15, all 128 key cols)
        float sacc[16][4];
#pragma unroll
        for (int ni = 0; ni < 16; ni++)
#pragma unroll
            for (int c = 0; c < 4; c++) sacc[ni][c] = 0.f;
#pragma unroll
        for (int ks = 0; ks < 8; ks++) {
            const int k = ks * 8;
            uint32_t af[4];
            af[0] = __float_as_uint(Qs[(rb + g    ) * FA_QK_S + k + t4    ]);
            af[1] = __float_as_uint(Qs[(rb + g + 8) * FA_QK_S + k + t4    ]);
            af[2] = __float_as_uint(Qs[(rb + g    ) * FA_QK_S + k + t4 + 4]);
            af[3] = __float_as_uint(Qs[(rb + g + 8) * FA_QK_S + k + t4 + 4]);
#pragma unroll
            for (int ni = 0; ni < 16; ni++) {
                uint32_t bf[2];
                bf[0] = __float_as_uint(Ks[(ni * 8 + g) * FA_QK_S + k + t4    ]);
                bf[1] = __float_as_uint(Ks[(ni * 8 + g) * FA_QK_S + k + t4 + 4]);
                mma_tf32(sacc[ni], af, bf);
            }
        }

        // scale + mask + tile row-max
        float tm0 = -1e30f, tm1 = -1e30f;
#pragma unroll
        for (int ni = 0; ni < 16; ni++) {
            const int c0 = ni * 8 + t4 * 2, c1 = c0 + 1;
            const bool m0 = (Ms[c0] == 0), m1 = (Ms[c1] == 0);
            float s0 = sacc[ni][0] * 0.125f; if (m0) s0 = -1e10f;
            float s1 = sacc[ni][1] * 0.125f; if (m1) s1 = -1e10f;
            float s2 = sacc[ni][2] * 0.125f; if (m0) s2 = -1e10f;
            float s3 = sacc[ni][3] * 0.125f; if (m1) s3 = -1e10f;
            sacc[ni][0] = s0; sacc[ni][1] = s1; sacc[ni][2] = s2; sacc[ni][3] = s3;
            tm0 = fmaxf(tm0, fmaxf(s0, s1));
            tm1 = fmaxf(tm1, fmaxf(s2, s3));
        }
        tm0 = fmaxf(tm0, __shfl_xor_sync(0xffffffffu, tm0, 1));
        tm0 = fmaxf(tm0, __shfl_xor_sync(0xffffffffu, tm0, 2));
        tm1 = fmaxf(tm1, __shfl_xor_sync(0xffffffffu, tm1, 1));
        tm1 = fmaxf(tm1, __shfl_xor_sync(0xffffffffu, tm1, 2));

        const float mn0 = fmaxf(mrow0, tm0), mn1 = fmaxf(mrow1, tm1);
        const float a0 = __expf(mrow0 - mn0), a1 = __expf(mrow1 - mn1);

        float ps0 = 0.f, ps1 = 0.f;
#pragma unroll
        for (int ni = 0; ni < 16; ni++) {
            const float e0 = __expf(sacc[ni][0] - mn0);
            const float e1 = __expf(sacc[ni][1] - mn0);
            const float e2 = __expf(sacc[ni][2] - mn1);
            const float e3 = __expf(sacc[ni][3] - mn1);
            ps0 += e0 + e1; ps1 += e2 + e3;
            float* p0 = Ps + (rb + g    ) * FA_P_S + ni * 8 + t4 * 2;
            p0[0] = f2tf32(e0); p0[1] = f2tf32(e1);
            float* p1 = Ps + (rb + g + 8) * FA_P_S + ni * 8 + t4 * 2;
            p1[0] = f2tf32(e2); p1[1] = f2tf32(e3);
        }
        ps0 += __shfl_xor_sync(0xffffffffu, ps0, 1);
        ps0 += __shfl_xor_sync(0xffffffffu, ps0, 2);
        ps1 += __shfl_xor_sync(0xffffffffu, ps1, 1);
        ps1 += __shfl_xor_sync(0xffffffffu, ps1, 2);

        lrow0 = lrow0 * a0 + ps0;
        lrow1 = lrow1 * a1 + ps1;
        mrow0 = mn0; mrow1 = mn1;
#pragma unroll
        for (int ni = 0; ni < 8; ni++) {
            oacc[ni][0] *= a0; oacc[ni][1] *= a0;
            oacc[ni][2] *= a1; oacc[ni][3] *= a1;
        }
        __syncwarp();   // P rows are per-warp: warp-level visibility suffices

        // O += P V
#pragma unroll
        for (int ks = 0; ks < 16; ks++) {
            const int k = ks * 8;
            uint32_t af[4];
            af[0] = __float_as_uint(Ps[(rb + g    ) * FA_P_S + k + t4    ]);
            af[1] = __float_as_uint(Ps[(rb + g + 8) * FA_P_S + k + t4    ]);
            af[2] = __float_as_uint(Ps[(rb + g    ) * FA_P_S + k + t4 + 4]);
            af[3] = __float_as_uint(Ps[(rb + g + 8) * FA_P_S + k + t4 + 4]);
#pragma unroll
            for (int ni = 0; ni < 8; ni++) {
                uint32_t bf[2];
                bf[0] = __float_as_uint(Vs[(k + t4    ) * FA_V_S + ni * 8 + g]);
                bf[1] = __float_as_uint(Vs[(k + t4 + 4) * FA_V_S + ni * 8 + g]);
                mma_tf32(oacc[ni], af, bf);
            }
        }
    }

    // normalize + scatter to (B,L,D)
    const float i0 = 1.f / lrow0, i1 = 1.f / lrow1;
    const int r0 = tileQ + rb + g, r1 = r0 + 8;
#pragma unroll
    for (int ni = 0; ni < 8; ni++) {
        const int d = ni * 8 + t4 * 2;
        *(float2*)(H + (size_t)(b * LSEQ + r0) * D_MODEL + h * DH + d) =
            make_float2(oacc[ni][0] * i0, oacc[ni][1] * i0);
        *(float2*)(H + (size_t)(b * LSEQ + r1) * D_MODEL + h * DH + d) =
            make_float2(oacc[ni][2] * i1, oacc[ni][3] * i1);
    }
}

// ---------------- weight transpose: out[n][k] = in[k][n] --------------------
__global__ __launch_bounds__(256) void transpose_k(
    const float* __restrict__ in, float* __restrict__ out, int K, int N)
{
    __shared__ float t[32][33];
    const int bn = blockIdx.x * 32, bk = blockIdx.y * 32;
    const int tx = threadIdx.x, ty = threadIdx.y;
#pragma unroll
    for (int i = ty; i < 32; i += 8)
        t[i][tx] = in[(size_t)(bk + i) * N + bn + tx];
    __syncthreads();
#pragma unroll
    for (int i = ty; i < 32; i += 8)
        out[(size_t)(bn + i) * K + bk + tx] = t[tx][i];
}

// ---------------- layernorm --------------------------------------------------
__global__ __launch_bounds__(256) void layernorm(
    const float* __restrict__ X, const float* __restrict__ g,
    const float* __restrict__ be, float* __restrict__ O)
{
    __shared__ float red[8];
    const int r = blockIdx.x;
    const int tid = threadIdx.x;
    const float4 v = *(const float4*)(X + (size_t)r * D_MODEL + tid * 4);

    float s = v.x + v.y + v.z + v.w;
#pragma unroll
    for (int o = 16; o > 0; o >>= 1) s += __shfl_xor_sync(0xffffffffu, s, o);
    if ((tid & 31) == 0) red[tid >> 5] = s;
    __syncthreads();
    s = 0.f;
#pragma unroll
    for (int i = 0; i < 8; i++) s += red[i];
    const float mu = s * (1.f / D_MODEL);
    __syncthreads();

    float dx = v.x - mu, dy = v.y - mu, dz = v.z - mu, dw = v.w - mu;
    float sq = dx * dx + dy * dy + dz * dz + dw * dw;
#pragma unroll
    for (int o = 16; o > 0; o >>= 1) sq += __shfl_xor_sync(0xffffffffu, sq, o);
    if ((tid & 31) == 0) red[tid >> 5] = sq;
    __syncthreads();
    sq = 0.f;
#pragma unroll
    for (int i = 0; i < 8; i++) sq += red[i];
    const float rs = rsqrtf(sq * (1.f / D_MODEL) + 1e-5f);

    const float4 gg = *(const float4*)(g + tid * 4);
    const float4 bb = *(const float4*)(be + tid * 4);
    float4 o;
    o.x = dx * rs * gg.x + bb.x;
    o.y = dy * rs * gg.y + bb.y;
    o.z = dz * rs * gg.z + bb.z;
    o.w = dw * rs * gg.w + bb.w;
    *(float4*)(O + (size_t)r * D_MODEL + tid * 4) = o;
}

// ---------------- launch -----------------------------------------------------
extern "C" void kernel_launch(void* const* d_in, const int* in_sizes, int n_in,
                              void* d_out, int out_size)
{
    const float* x   = (const float*)d_in[0];
    const int*   msk = (const int*)d_in[1];
    const float* Wq  = (const float*)d_in[2];
    const float* Wk  = (const float*)d_in[3];
    const float* Wv  = (const float*)d_in[4];
    const float* Wp  = (const float*)d_in[5];
    const float* bp  = (const float*)d_in[6];
    const float* W1  = (const float*)d_in[7];
    const float* b1  = (const float*)d_in[8];
    const float* W2  = (const float*)d_in[9];
    const float* b2  = (const float*)d_in[10];
    const float* g1  = (const float*)d_in[11];
    const float* be1 = (const float*)d_in[12];
    const float* g2  = (const float*)d_in[13];
    const float* be2 = (const float*)d_in[14];
    float* out = (float*)d_out;

    float *q, *k, *v, *hd, *tmp, *h, *ff, *wtqkv, *wtp, *wt1, *wt2;
    cudaGetSymbolAddress((void**)&q,     g_q);
    cudaGetSymbolAddress((void**)&k,     g_k);
    cudaGetSymbolAddress((void**)&v,     g_v);
    cudaGetSymbolAddress((void**)&hd,    g_heads);
    cudaGetSymbolAddress((void**)&tmp,   g_tmp);
    cudaGetSymbolAddress((void**)&h,     g_h);
    cudaGetSymbolAddress((void**)&ff,    g_ff);
    cudaGetSymbolAddress((void**)&wtqkv, g_wtqkv);
    cudaGetSymbolAddress((void**)&wtp,   g_wtp);
    cudaGetSymbolAddress((void**)&wt1,   g_wt1);
    cudaGetSymbolAddress((void**)&wt2,   g_wt2);

    static bool attr_done = false;
    if (!attr_done) {
        cudaFuncSetAttribute(gemm_mma<EPI_QKV>,
                             cudaFuncAttributeMaxDynamicSharedMemorySize, GM_SMEM_B);
        cudaFuncSetAttribute(gemm_mma<EPI_BIAS_RESID>,
                             cudaFuncAttributeMaxDynamicSharedMemorySize, GM_SMEM_B);
        cudaFuncSetAttribute(gemm_mma<EPI_BIAS_RELU>,
                             cudaFuncAttributeMaxDynamicSharedMemorySize, GM_SMEM_B);
        cudaFuncSetAttribute(flash_attn,
                             cudaFuncAttributeMaxDynamicSharedMemorySize, FA_SMEM_B);
        attr_done = true;
    }

    dim3 blk(256);
    dim3 tb(32, 8);

    // weight transposes -> (N,K) layouts
    transpose_k<<<dim3(32, 32), tb>>>(Wq, wtqkv + 0 * 1024 * 1024, D_MODEL, D_MODEL);
    transpose_k<<<dim3(32, 32), tb>>>(Wk, wtqkv + 1 * 1024 * 1024, D_MODEL, D_MODEL);
    transpose_k<<<dim3(32, 32), tb>>>(Wv, wtqkv + 2 * 1024 * 1024, D_MODEL, D_MODEL);
    transpose_k<<<dim3(32, 32), tb>>>(Wp, wtp, D_MODEL, D_MODEL);
    transpose_k<<<dim3(128, 32), tb>>>(W1, wt1, D_MODEL, DFF);   // 1024x4096 -> 4096x1024
    transpose_k<<<dim3(32, 128), tb>>>(W2, wt2, DFF, D_MODEL);   // 4096x1024 -> 1024x4096

    // fused QKV projection (M=4096, N=3072, K=1024), scatter to head layout
    gemm_mma<EPI_QKV><<<dim3(24, 32), blk, GM_SMEM_B>>>(
        x, wtqkv, nullptr, 3072, 1024, nullptr, nullptr, q, k, v);

    // fused attention: QK^T/8 -> masked online softmax -> P V  (per head/q-tile)
    flash_attn<<<dim3(8, ZHEADS), blk, FA_SMEM_B>>>(q, k, v, msk, hd);

    // proj + bias + residual, LN1
    gemm_mma<EPI_BIAS_RESID><<<dim3(8, 32), blk, GM_SMEM_B>>>(
        hd, wtp, tmp, 1024, 1024, bp, x, nullptr, nullptr, nullptr);
    layernorm<<<MROWS, blk>>>(tmp, g1, be1, h);

    // FF1 (ReLU), FF2 + bias + residual, LN2
    gemm_mma<EPI_BIAS_RELU><<<dim3(32, 32), blk, GM_SMEM_B>>>(
        h, wt1, ff, 4096, 1024, b1, nullptr, nullptr, nullptr, nullptr);
    gemm_mma<EPI_BIAS_RESID><<<dim3(8, 32), blk, GM_SMEM_B>>>(
        ff, wt2, tmp, 1024, 4096, b2, h, nullptr, nullptr, nullptr);
    layernorm<<<MROWS, blk>>>(tmp, g2, be2, out);
}